// round 1
// baseline (speedup 1.0000x reference)
#include <cuda_runtime.h>
#include <cstdint>

// ---------------- problem constants ----------------
#define RNN_B 256
#define RNN_T 256
#define RNN_I 5
#define RNN_H 2048
#define RNN_O 4

#define GRID_CTAS 128      // CTAs; each owns NJ=16 output columns of Wrec
#define NTHREADS  128      // 4 warps
#define NJ        16       // H / GRID_CTAS
#define KC        32       // k-chunk (double buffered via cp.async)
#define NKCH      64       // H / KC

#define F_ALPHA 0.1f
#define F_BETA  0.9f

// ---------------- shared memory layout (bytes) ----------------
#define WREC_OFF   0                              // NJ*H floats       = 131072 B
#define UNION_OFF  (WREC_OFF + NJ * RNN_H * 4)    // 2*KC*B floats     =  65536 B
#define UNION_BYTES (2 * KC * RNN_B * 4)
#define NOISE_OFF  (UNION_OFF)                    // B*17 floats (aliases hs)
#define OUTS_OFF   (UNION_OFF + RNN_B * 17 * 4)   // B*17 floats (aliases hs)
#define XS_OFF     (UNION_OFF + UNION_BYTES)      // B*I floats        =   5120 B
#define WIN_OFF    (XS_OFF + RNN_B * RNN_I * 4)   // NJ*I floats       =    320 B
#define LOG_OFF    (WIN_OFF + NJ * RNN_I * 4)     // 8 floats
#define SMEM_BYTES (LOG_OFF + 8 * 4)              // = 202080 B

#define HID_ELEMS ((size_t)RNN_B * RNN_T * RNN_H) // 134217728

// ---------------- global scratch (static; no allocation) ----------------
static __device__ float    g_h[2 * RNN_H * RNN_B];  // [buf][k][b]  (k-major, b contiguous)
static __device__ unsigned g_count;                  // returns to 0 after every barrier
static __device__ unsigned g_release;                // monotonic; compared relatively

// ---------------- helpers ----------------
__device__ __forceinline__ void cp_async16(void* dst, const void* src) {
    uint32_t sa = (uint32_t)__cvta_generic_to_shared(dst);
    asm volatile("cp.async.cg.shared.global [%0], [%1], 16;\n" :: "r"(sa), "l"(src) : "memory");
}

__device__ __forceinline__ void grid_barrier() {
    __syncthreads();
    __threadfence();
    if (threadIdx.x == 0) {
        volatile unsigned* relp = (volatile unsigned*)&g_release;
        unsigned rel  = *relp;                       // read BEFORE arriving
        unsigned prev = atomicAdd(&g_count, 1u);
        if (prev == (unsigned)(GRID_CTAS - 1)) {
            atomicExch(&g_count, 0u);                // reset for next barrier / next launch
            __threadfence();
            atomicAdd(&g_release, 1u);               // release
        } else {
            while (*relp == rel) { }
        }
    }
    __syncthreads();
    __threadfence();
}

// ---------------- persistent kernel ----------------
__global__ void __launch_bounds__(NTHREADS, 1)
rnn_persistent_kernel(const float* __restrict__ x,     // [B,T,I]
                      const float* __restrict__ Win,   // [H,I]
                      const float* __restrict__ Wrec,  // [H,H]
                      const float* __restrict__ Wout,  // [O,H]
                      const float* __restrict__ noise, // [T,B,H]
                      float* __restrict__ out)         // hiddens [B,T,H] ++ outputs [B,T,O]
{
    extern __shared__ char smem[];
    float* Wrec_s   = (float*)(smem + WREC_OFF);
    float* hs       = (float*)(smem + UNION_OFF);
    float* noise_s  = (float*)(smem + NOISE_OFF);
    float* out_s    = (float*)(smem + OUTS_OFF);
    float* xs       = (float*)(smem + XS_OFF);
    float* Win_s    = (float*)(smem + WIN_OFF);
    float* logits_s = (float*)(smem + LOG_OFF);

    const int tid = threadIdx.x;
    const int tx  = tid & 31;
    const int wy  = tid >> 5;          // warp id 0..3; warp owns columns 4*wy..4*wy+3 (local)
    const int c   = blockIdx.x;
    const int jc  = c * NJ;            // first global column owned by this CTA

    // ---- one-time loads ----
    for (int i = tid; i < NJ * RNN_H; i += NTHREADS) Wrec_s[i] = Wrec[jc * RNN_H + i];
    for (int i = tid; i < NJ * RNN_I; i += NTHREADS) Win_s[i]  = Win[jc * RNN_I + i];
    // zero h buffer 0 (owned slice)
    for (int i = tid; i < NJ * RNN_B; i += NTHREADS) {
        int jl = i >> 8, b = i & 255;
        g_h[(jc + jl) * RNN_B + b] = 0.0f;
    }

    float hprev[4][2][4];
    #pragma unroll
    for (int jj = 0; jj < 4; ++jj)
        #pragma unroll
        for (int m = 0; m < 2; ++m)
            #pragma unroll
            for (int bb = 0; bb < 4; ++bb) hprev[jj][m][bb] = 0.0f;

    grid_barrier();   // barrier #0: h buffer 0 visible chip-wide

    for (int t = 0; t < RNN_T; ++t) {
        // ---- softmax readout for previous step (post-barrier, h row t-1 complete) ----
        if (t > 0) {
            const int tp = t - 1;
            const int b0 = 2 * c;
            const int bb = wy >> 1;
            const int b  = b0 + bb;
            const int o0 = 2 * (wy & 1);
            const float* hrow = out + ((size_t)b * RNN_T + tp) * RNN_H;
            const float* w0 = Wout + (size_t)o0 * RNN_H;
            const float* w1 = Wout + (size_t)(o0 + 1) * RNN_H;
            float a0 = 0.f, a1 = 0.f;
            #pragma unroll 4
            for (int k = tx; k < RNN_H; k += 32) {
                float hv = __ldcg(hrow + k);   // L2: written by other CTAs last step
                a0 += hv * w0[k];
                a1 += hv * w1[k];
            }
            #pragma unroll
            for (int s = 16; s; s >>= 1) {
                a0 += __shfl_xor_sync(0xffffffffu, a0, s);
                a1 += __shfl_xor_sync(0xffffffffu, a1, s);
            }
            if (tx == 0) { logits_s[bb * 4 + o0] = a0; logits_s[bb * 4 + o0 + 1] = a1; }
            __syncthreads();
            if (tid < 2) {
                float l0 = logits_s[tid * 4 + 0], l1 = logits_s[tid * 4 + 1];
                float l2 = logits_s[tid * 4 + 2], l3 = logits_s[tid * 4 + 3];
                float mx = fmaxf(fmaxf(l0, l1), fmaxf(l2, l3));
                float e0 = expf(l0 - mx), e1 = expf(l1 - mx), e2 = expf(l2 - mx), e3 = expf(l3 - mx);
                float inv = 1.0f / (e0 + e1 + e2 + e3);
                size_t base = HID_ELEMS + ((size_t)(b0 + tid) * RNN_T + tp) * RNN_O;
                out[base + 0] = e0 * inv; out[base + 1] = e1 * inv;
                out[base + 2] = e2 * inv; out[base + 3] = e3 * inv;
            }
            __syncthreads();
        }

        // ---- stage x[:,t,:] ----
        for (int i = tid; i < RNN_B * RNN_I; i += NTHREADS) {
            int b = i / RNN_I, ii = i % RNN_I;
            xs[i] = x[((size_t)b * RNN_T + t) * RNN_I + ii];
        }

        const int rbuf = t & 1;
        const float* hsrc = g_h + (size_t)rbuf * RNN_H * RNN_B;

        float acc[4][2][4];
        #pragma unroll
        for (int jj = 0; jj < 4; ++jj)
            #pragma unroll
            for (int m = 0; m < 2; ++m)
                #pragma unroll
                for (int bb = 0; bb < 4; ++bb) acc[jj][m][bb] = 0.0f;

        // prefetch chunk 0 (cp.async bypasses L1 -> no cross-step staleness)
        {
            const char* src = (const char*)hsrc;
            char* dst = (char*)hs;
            for (int i = tid * 16; i < KC * RNN_B * 4; i += NTHREADS * 16)
                cp_async16(dst + i, src + i);
            asm volatile("cp.async.commit_group;\n" ::: "memory");
        }

        // ---- main recurrent GEMM: pre[b, jc..jc+15] += Wrec_s . h ----
        for (int ch = 0; ch < NKCH; ++ch) {
            if (ch + 1 < NKCH) {
                const char* src = (const char*)(hsrc + (size_t)(ch + 1) * KC * RNN_B);
                char* dst = (char*)hs + (size_t)((ch + 1) & 1) * (KC * RNN_B * 4);
                for (int i = tid * 16; i < KC * RNN_B * 4; i += NTHREADS * 16)
                    cp_async16(dst + i, src + i);
                asm volatile("cp.async.commit_group;\n" ::: "memory");
                asm volatile("cp.async.wait_group 1;\n" ::: "memory");
            } else {
                asm volatile("cp.async.wait_group 0;\n" ::: "memory");
            }
            __syncthreads();

            const float* hc = hs + (ch & 1) * (KC * RNN_B);
            #pragma unroll 2
            for (int kk = 0; kk < KC; kk += 4) {
                const int kg = ch * KC + kk;
                float wr[4][4];
                #pragma unroll
                for (int jj = 0; jj < 4; ++jj) {
                    float4 v = *(const float4*)&Wrec_s[(4 * wy + jj) * RNN_H + kg];
                    wr[jj][0] = v.x; wr[jj][1] = v.y; wr[jj][2] = v.z; wr[jj][3] = v.w;
                }
                #pragma unroll
                for (int q = 0; q < 4; ++q) {
                    #pragma unroll
                    for (int m = 0; m < 2; ++m) {
                        float4 hv = *(const float4*)&hc[(kk + q) * RNN_B + 4 * tx + 128 * m];
                        #pragma unroll
                        for (int jj = 0; jj < 4; ++jj) {
                            acc[jj][m][0] += wr[jj][q] * hv.x;
                            acc[jj][m][1] += wr[jj][q] * hv.y;
                            acc[jj][m][2] += wr[jj][q] * hv.z;
                            acc[jj][m][3] += wr[jj][q] * hv.w;
                        }
                    }
                }
            }
            __syncthreads();   // protects buffer reuse by next prefetch
        }

        // ---- Phase A: coalesced noise stage (aliases hs; GEMM finished) ----
        for (int i = tid; i < RNN_B * NJ; i += NTHREADS) {
            int b = i >> 4, jl = i & 15;
            noise_s[b * 17 + jl] = noise[((size_t)t * RNN_B + b) * RNN_H + jc + jl];
        }
        __syncthreads();

        // ---- Phase B: leaky update, all in registers ----
        #pragma unroll
        for (int jj = 0; jj < 4; ++jj) {
            const int jl = 4 * wy + jj;
            #pragma unroll
            for (int m = 0; m < 2; ++m) {
                #pragma unroll
                for (int bb = 0; bb < 4; ++bb) {
                    const int b = 4 * tx + bb + 128 * m;
                    float itv = 0.0f;
                    #pragma unroll
                    for (int ii = 0; ii < RNN_I; ++ii)
                        itv += xs[b * RNN_I + ii] * Win_s[jl * RNN_I + ii];
                    float pre = acc[jj][m][bb] + itv + noise_s[b * 17 + jl];
                    float hn  = F_ALPHA * fmaxf(pre, 0.0f) + F_BETA * hprev[jj][m][bb];
                    hprev[jj][m][bb] = hn;
                    out_s[b * 17 + jl] = hn;
                }
            }
        }
        __syncthreads();

        // ---- Phase C: coalesced writeback (hiddens + transposed h state) ----
        const int wbuf = rbuf ^ 1;
        for (int i = tid; i < RNN_B * NJ; i += NTHREADS) {
            int b = i >> 4, jl = i & 15;
            out[((size_t)b * RNN_T + t) * RNN_H + jc + jl] = out_s[b * 17 + jl];
        }
        for (int i = tid; i < RNN_B * NJ; i += NTHREADS) {
            int jl = i >> 8, b = i & 255;
            g_h[(size_t)wbuf * RNN_H * RNN_B + (jc + jl) * RNN_B + b] = out_s[b * 17 + jl];
        }

        grid_barrier();
    }

    // ---- final readout for t = T-1 ----
    {
        const int tp = RNN_T - 1;
        const int b0 = 2 * c;
        const int bb = wy >> 1;
        const int b  = b0 + bb;
        const int o0 = 2 * (wy & 1);
        const float* hrow = out + ((size_t)b * RNN_T + tp) * RNN_H;
        const float* w0 = Wout + (size_t)o0 * RNN_H;
        const float* w1 = Wout + (size_t)(o0 + 1) * RNN_H;
        float a0 = 0.f, a1 = 0.f;
        #pragma unroll 4
        for (int k = tx; k < RNN_H; k += 32) {
            float hv = __ldcg(hrow + k);
            a0 += hv * w0[k];
            a1 += hv * w1[k];
        }
        #pragma unroll
        for (int s = 16; s; s >>= 1) {
            a0 += __shfl_xor_sync(0xffffffffu, a0, s);
            a1 += __shfl_xor_sync(0xffffffffu, a1, s);
        }
        if (tx == 0) { logits_s[bb * 4 + o0] = a0; logits_s[bb * 4 + o0 + 1] = a1; }
        __syncthreads();
        if (tid < 2) {
            float l0 = logits_s[tid * 4 + 0], l1 = logits_s[tid * 4 + 1];
            float l2 = logits_s[tid * 4 + 2], l3 = logits_s[tid * 4 + 3];
            float mx = fmaxf(fmaxf(l0, l1), fmaxf(l2, l3));
            float e0 = expf(l0 - mx), e1 = expf(l1 - mx), e2 = expf(l2 - mx), e3 = expf(l3 - mx);
            float inv = 1.0f / (e0 + e1 + e2 + e3);
            size_t base = HID_ELEMS + ((size_t)(b0 + tid) * RNN_T + tp) * RNN_O;
            out[base + 0] = e0 * inv; out[base + 1] = e1 * inv;
            out[base + 2] = e2 * inv; out[base + 3] = e3 * inv;
        }
    }
}

// ---------------- launch ----------------
extern "C" void kernel_launch(void* const* d_in, const int* in_sizes, int n_in,
                              void* d_out, int out_size) {
    const float* x     = (const float*)d_in[0];   // [B,T,I]
    const float* Win   = (const float*)d_in[1];   // [H,I]
    const float* Wrec  = (const float*)d_in[2];   // [H,H]
    const float* Wout  = (const float*)d_in[3];   // [O,H]
    const float* noise = (const float*)d_in[4];   // [T,B,H]
    float* out = (float*)d_out;

    cudaFuncSetAttribute(rnn_persistent_kernel,
                         cudaFuncAttributeMaxDynamicSharedMemorySize, SMEM_BYTES);
    rnn_persistent_kernel<<<GRID_CTAS, NTHREADS, SMEM_BYTES>>>(x, Win, Wrec, Wout, noise, out);
}

// round 4
// speedup vs baseline: 2.0814x; 2.0814x over previous
#include <cuda_runtime.h>
#include <cuda_bf16.h>
#include <cstdint>

// ---------------- problem constants ----------------
#define RNN_B 256
#define RNN_T 256
#define RNN_I 5
#define RNN_H 2048
#define RNN_O 4

#define GRID_CTAS 128
#define NTHREADS  256      // 8 warps

// GEMM decomposition: 32 j-tiles (64 rows) x 4 k-slices (512 k)
#define JT_ROWS 64
#define KSLICE  512
#define NKSL    4
#define KC      32         // k chunk (double buffered)
#define NCH     (KSLICE / KC)   // 16

// epilogue ownership: 16 j-rows per CTA
#define NJ 16

#define F_ALPHA 0.1f
#define F_BETA  0.9f

// SMEM row pads (bank-conflict-free fragment loads)
#define W_PITCH 520        // halfwords per Wrec row (512 + 8)
#define H_PITCH 40         // halfwords per h row (32 + 8)

// ---------------- shared memory layout (bytes) ----------------
#define WH_OFF   0                                   // 64*520*2 = 66560
#define WL_OFF   (WH_OFF + JT_ROWS * W_PITCH * 2)    // 66560
#define HS_OFF   (WL_OFF + JT_ROWS * W_PITCH * 2)    // 133120
#define HS_BUF_STRIDE (2 * RNN_B * H_PITCH * 2)      // 40960 (hi+lo arrays)
#define HS_ARR_STRIDE (RNN_B * H_PITCH * 2)          // 20480
#define HS_BYTES (2 * HS_BUF_STRIDE)                 // 81920
#define XS_OFF   (HS_OFF + HS_BYTES)                 // 215040 (5120)
#define WIN_OFF  (XS_OFF + RNN_B * RNN_I * 4)        // 220160 (320)
#define LOG_OFF  (WIN_OFF + NJ * RNN_I * 4)          // 220480 (32)
#define SMEM_BYTES (LOG_OFF + 32)                    // 220512
// epilogue staging aliases the h region (GEMM done by then)
#define NOISE_OFF (HS_OFF)                           // 256*17*4 = 17408
#define OUTS_OFF  (HS_OFF + RNN_B * 17 * 4)          // 17408

#define HID_ELEMS ((size_t)RNN_B * RNN_T * RNN_H)    // 134217728

// ---------------- global scratch (static; no allocation) ----------------
static __device__ __nv_bfloat16 g_hhi[2 * RNN_B * RNN_H];   // [par][b][k]
static __device__ __nv_bfloat16 g_hlo[2 * RNN_B * RNN_H];
static __device__ float pre_part[NKSL * RNN_H * RNN_B];     // [ks][j][b]
static __device__ unsigned g_count;
static __device__ unsigned g_release;

// ---------------- helpers ----------------
__device__ __forceinline__ void cp_async16(void* dst, const void* src) {
    uint32_t sa = (uint32_t)__cvta_generic_to_shared(dst);
    asm volatile("cp.async.cg.shared.global [%0], [%1], 16;\n" :: "r"(sa), "l"(src) : "memory");
}

__device__ __forceinline__ void grid_barrier() {
    __syncthreads();
    __threadfence();
    if (threadIdx.x == 0) {
        volatile unsigned* relp = (volatile unsigned*)&g_release;
        unsigned rel  = *relp;
        unsigned prev = atomicAdd(&g_count, 1u);
        if (prev == (unsigned)(GRID_CTAS - 1)) {
            atomicExch(&g_count, 0u);
            __threadfence();
            atomicAdd(&g_release, 1u);
        } else {
            while (*relp == rel) { }
        }
    }
    __syncthreads();
    __threadfence();
}

#define MMA_BF16(d, a0, a1, a2, a3, b0, b1)                                   \
    asm volatile("mma.sync.aligned.m16n8k16.row.col.f32.bf16.bf16.f32 "       \
                 "{%0,%1,%2,%3}, {%4,%5,%6,%7}, {%8,%9}, {%0,%1,%2,%3};"      \
                 : "+f"((d)[0]), "+f"((d)[1]), "+f"((d)[2]), "+f"((d)[3])     \
                 : "r"(a0), "r"(a1), "r"(a2), "r"(a3), "r"(b0), "r"(b1))

__device__ __forceinline__ uint32_t lds_u32(const __nv_bfloat16* base, int hw_idx) {
    return *(const uint32_t*)(base + hw_idx);
}

// ---------------- persistent kernel ----------------
__global__ void __launch_bounds__(NTHREADS, 1)
rnn_persistent_kernel(const float* __restrict__ x,     // [B,T,I]
                      const float* __restrict__ Win,   // [H,I]
                      const float* __restrict__ Wrec,  // [H,H]
                      const float* __restrict__ Wout,  // [O,H]
                      const float* __restrict__ noise, // [T,B,H]
                      float* __restrict__ out)         // hiddens [B,T,H] ++ outputs [B,T,O]
{
    extern __shared__ char smem[];
    __nv_bfloat16* Whi_s = (__nv_bfloat16*)(smem + WH_OFF);
    __nv_bfloat16* Wlo_s = (__nv_bfloat16*)(smem + WL_OFF);
    float* xs       = (float*)(smem + XS_OFF);
    float* Win_s    = (float*)(smem + WIN_OFF);
    float* logits_s = (float*)(smem + LOG_OFF);
    float* noise_s  = (float*)(smem + NOISE_OFF);
    float* out_s    = (float*)(smem + OUTS_OFF);

    const int tid  = threadIdx.x;
    const int lane = tid & 31;
    const int w    = tid >> 5;          // 0..7
    const int c    = blockIdx.x;

    // GEMM role
    const int jt = c >> 2;              // j-tile 0..31
    const int ks = c & 3;               // k-slice 0..3
    const int K0 = ks * KSLICE;
    const int jw = (w & 3) * 16;        // warp j offset within 64-row tile
    const int bw = (w >> 2) * 128;      // warp b offset
    // epilogue role
    const int jc = c * NJ;

    // ---- one-time: split Wrec slice into SMEM bf16 hi/lo ----
    for (int i = tid; i < JT_ROWS * KSLICE; i += NTHREADS) {
        int jl = i >> 9, kk = i & (KSLICE - 1);
        float wv = Wrec[(size_t)(jt * JT_ROWS + jl) * RNN_H + K0 + kk];
        __nv_bfloat16 hi = __float2bfloat16_rn(wv);
        __nv_bfloat16 lo = __float2bfloat16_rn(wv - __bfloat162float(hi));
        Whi_s[jl * W_PITCH + kk] = hi;
        Wlo_s[jl * W_PITCH + kk] = lo;
    }
    for (int i = tid; i < NJ * RNN_I; i += NTHREADS) Win_s[i] = Win[jc * RNN_I + i];
    // zero h parity 0 (owned slice: 2048 u32 per CTA per array)
    {
        uint32_t* ph = (uint32_t*)g_hhi;
        uint32_t* pl = (uint32_t*)g_hlo;
        for (int i = tid; i < 2048; i += NTHREADS) { ph[c * 2048 + i] = 0u; pl[c * 2048 + i] = 0u; }
    }

    float hprev[NJ];
    #pragma unroll
    for (int i = 0; i < NJ; ++i) hprev[i] = 0.0f;

    // fragment base offsets (halfword indices)
    const int a_off = (jw + (lane >> 2)) * W_PITCH + (lane & 3) * 2;
    const int b_off = (bw + (lane >> 2)) * H_PITCH + (lane & 3) * 2;

    grid_barrier();   // h parity 0 + Wrec smem visible

    for (int t = 0; t < RNN_T; ++t) {
        const int rpar = t & 1;
        const __nv_bfloat16* ghi = g_hhi + (size_t)rpar * RNN_B * RNN_H;
        const __nv_bfloat16* glo = g_hlo + (size_t)rpar * RNN_B * RNN_H;

        float acc[16][4];
        #pragma unroll
        for (int nf = 0; nf < 16; ++nf)
            #pragma unroll
            for (int q = 0; q < 4; ++q) acc[nf][q] = 0.0f;

        // prefetch chunk 0
        {
            char* dhi = smem + HS_OFF;                      // buf 0, arr hi
            char* dlo = smem + HS_OFF + HS_ARR_STRIDE;      // buf 0, arr lo
            const char* shi = (const char*)(ghi + K0);
            const char* slo = (const char*)(glo + K0);
            for (int i = tid; i < 1024; i += NTHREADS) {
                int row = i >> 2, q = i & 3;
                cp_async16(dhi + row * (H_PITCH * 2) + q * 16, shi + (size_t)row * (RNN_H * 2) + q * 16);
                cp_async16(dlo + row * (H_PITCH * 2) + q * 16, slo + (size_t)row * (RNN_H * 2) + q * 16);
            }
            asm volatile("cp.async.commit_group;\n" ::: "memory");
        }

        // ---- K-slice GEMM ----
        for (int ch = 0; ch < NCH; ++ch) {
            if (ch + 1 < NCH) {
                char* dhi = smem + HS_OFF + ((ch + 1) & 1) * HS_BUF_STRIDE;
                char* dlo = dhi + HS_ARR_STRIDE;
                const char* shi = (const char*)(ghi + K0 + (ch + 1) * KC);
                const char* slo = (const char*)(glo + K0 + (ch + 1) * KC);
                for (int i = tid; i < 1024; i += NTHREADS) {
                    int row = i >> 2, q = i & 3;
                    cp_async16(dhi + row * (H_PITCH * 2) + q * 16, shi + (size_t)row * (RNN_H * 2) + q * 16);
                    cp_async16(dlo + row * (H_PITCH * 2) + q * 16, slo + (size_t)row * (RNN_H * 2) + q * 16);
                }
                asm volatile("cp.async.commit_group;\n" ::: "memory");
                asm volatile("cp.async.wait_group 1;\n" ::: "memory");
            } else {
                asm volatile("cp.async.wait_group 0;\n" ::: "memory");
            }
            __syncthreads();

            const __nv_bfloat16* hhi = (const __nv_bfloat16*)(smem + HS_OFF + (ch & 1) * HS_BUF_STRIDE);
            const __nv_bfloat16* hlo = (const __nv_bfloat16*)((const char*)hhi + HS_ARR_STRIDE);

            #pragma unroll
            for (int kk = 0; kk < KC; kk += 16) {
                const int ka = ch * KC + kk;   // halfword col into Wrec_s
                uint32_t ah0 = lds_u32(Whi_s, a_off + ka);
                uint32_t ah1 = lds_u32(Whi_s, a_off + ka + 8 * W_PITCH);
                uint32_t ah2 = lds_u32(Whi_s, a_off + ka + 8);
                uint32_t ah3 = lds_u32(Whi_s, a_off + ka + 8 * W_PITCH + 8);
                uint32_t al0 = lds_u32(Wlo_s, a_off + ka);
                uint32_t al1 = lds_u32(Wlo_s, a_off + ka + 8 * W_PITCH);
                uint32_t al2 = lds_u32(Wlo_s, a_off + ka + 8);
                uint32_t al3 = lds_u32(Wlo_s, a_off + ka + 8 * W_PITCH + 8);
                #pragma unroll
                for (int nf = 0; nf < 16; ++nf) {
                    const int bbase = b_off + nf * 8 * H_PITCH + kk;
                    uint32_t bh0 = lds_u32(hhi, bbase);
                    uint32_t bh1 = lds_u32(hhi, bbase + 8);
                    uint32_t bl0 = lds_u32(hlo, bbase);
                    uint32_t bl1 = lds_u32(hlo, bbase + 8);
                    MMA_BF16(acc[nf], ah0, ah1, ah2, ah3, bh0, bh1);
                    MMA_BF16(acc[nf], ah0, ah1, ah2, ah3, bl0, bl1);
                    MMA_BF16(acc[nf], al0, al1, al2, al3, bh0, bh1);
                }
            }
            __syncthreads();
        }

        // ---- store partials ----
        {
            const int j0  = jt * JT_ROWS + jw + (lane >> 2);
            const int b0g = bw + (lane & 3) * 2;
            #pragma unroll
            for (int nf = 0; nf < 16; ++nf) {
                const int b = b0g + nf * 8;
                float2 v0 = make_float2(acc[nf][0], acc[nf][1]);
                float2 v1 = make_float2(acc[nf][2], acc[nf][3]);
                *(float2*)&pre_part[((size_t)ks * RNN_H + j0    ) * RNN_B + b] = v0;
                *(float2*)&pre_part[((size_t)ks * RNN_H + j0 + 8) * RNN_B + b] = v1;
            }
        }

        // ---- softmax readout for t-1 (hide behind stragglers) ----
        if (t > 0) {
            const int tp = t - 1;
            const int b0 = 2 * c;
            if (w < 4) {
                const int bb = w >> 1;
                const int b  = b0 + bb;
                const int o0 = 2 * (w & 1);
                const float* hrow = out + ((size_t)b * RNN_T + tp) * RNN_H;
                const float* w0 = Wout + (size_t)o0 * RNN_H;
                const float* w1 = Wout + (size_t)(o0 + 1) * RNN_H;
                float a0 = 0.f, a1 = 0.f;
                #pragma unroll 4
                for (int k = lane; k < RNN_H; k += 32) {
                    float hv = __ldcg(hrow + k);
                    a0 += hv * w0[k];
                    a1 += hv * w1[k];
                }
                #pragma unroll
                for (int s = 16; s; s >>= 1) {
                    a0 += __shfl_xor_sync(0xffffffffu, a0, s);
                    a1 += __shfl_xor_sync(0xffffffffu, a1, s);
                }
                if (lane == 0) { logits_s[bb * 4 + o0] = a0; logits_s[bb * 4 + o0 + 1] = a1; }
            }
            __syncthreads();
            if (tid < 2) {
                float l0 = logits_s[tid * 4 + 0], l1 = logits_s[tid * 4 + 1];
                float l2 = logits_s[tid * 4 + 2], l3 = logits_s[tid * 4 + 3];
                float mx = fmaxf(fmaxf(l0, l1), fmaxf(l2, l3));
                float e0 = expf(l0 - mx), e1 = expf(l1 - mx), e2 = expf(l2 - mx), e3 = expf(l3 - mx);
                float inv = 1.0f / (e0 + e1 + e2 + e3);
                size_t base = HID_ELEMS + ((size_t)(b0 + tid) * RNN_T + tp) * RNN_O;
                out[base + 0] = e0 * inv; out[base + 1] = e1 * inv;
                out[base + 2] = e2 * inv; out[base + 3] = e3 * inv;
            }
            __syncthreads();
        }

        grid_barrier();   // partials complete chip-wide

        // ---- epilogue: stage x and noise (coalesced) ----
        for (int i = tid; i < RNN_B * RNN_I; i += NTHREADS) {
            int b = i / RNN_I, ii = i % RNN_I;
            xs[i] = x[((size_t)b * RNN_T + t) * RNN_I + ii];
        }
        for (int i = tid; i < RNN_B * NJ; i += NTHREADS) {
            int b = i >> 4, jl = i & 15;
            noise_s[b * 17 + jl] = noise[((size_t)t * RNN_B + b) * RNN_H + jc + jl];
        }
        __syncthreads();

        // ---- leaky update: thread = batch b, iter = local j ----
        {
            const int b = tid;
            #pragma unroll
            for (int jl = 0; jl < NJ; ++jl) {
                const size_t pbase = (size_t)(jc + jl) * RNN_B + b;
                float pre = __ldcg(&pre_part[0 * (size_t)RNN_H * RNN_B + pbase])
                          + __ldcg(&pre_part[1 * (size_t)RNN_H * RNN_B + pbase])
                          + __ldcg(&pre_part[2 * (size_t)RNN_H * RNN_B + pbase])
                          + __ldcg(&pre_part[3 * (size_t)RNN_H * RNN_B + pbase]);
                float itv = 0.0f;
                #pragma unroll
                for (int ii = 0; ii < RNN_I; ++ii)
                    itv += xs[b * RNN_I + ii] * Win_s[jl * RNN_I + ii];
                pre += itv + noise_s[b * 17 + jl];
                float hn = F_ALPHA * fmaxf(pre, 0.0f) + F_BETA * hprev[jl];
                hprev[jl] = hn;
                out_s[b * 17 + jl] = hn;
            }
        }
        __syncthreads();

        // ---- coalesced writeback: fp32 hidden + split-bf16 state ----
        {
            const int wpar = rpar ^ 1;
            __nv_bfloat16* dhi = g_hhi + (size_t)wpar * RNN_B * RNN_H;
            __nv_bfloat16* dlo = g_hlo + (size_t)wpar * RNN_B * RNN_H;
            for (int i = tid; i < RNN_B * NJ; i += NTHREADS) {
                int b = i >> 4, jl = i & 15;
                float hv = out_s[b * 17 + jl];
                out[((size_t)b * RNN_T + t) * RNN_H + jc + jl] = hv;
                __nv_bfloat16 hi = __float2bfloat16_rn(hv);
                __nv_bfloat16 lo = __float2bfloat16_rn(hv - __bfloat162float(hi));
                dhi[(size_t)b * RNN_H + jc + jl] = hi;
                dlo[(size_t)b * RNN_H + jc + jl] = lo;
            }
        }

        grid_barrier();   // h(t) complete chip-wide
    }

    // ---- final softmax for t = T-1 ----
    {
        const int tp = RNN_T - 1;
        const int b0 = 2 * c;
        if (w < 4) {
            const int bb = w >> 1;
            const int b  = b0 + bb;
            const int o0 = 2 * (w & 1);
            const float* hrow = out + ((size_t)b * RNN_T + tp) * RNN_H;
            const float* w0 = Wout + (size_t)o0 * RNN_H;
            const float* w1 = Wout + (size_t)(o0 + 1) * RNN_H;
            float a0 = 0.f, a1 = 0.f;
            #pragma unroll 4
            for (int k = lane; k < RNN_H; k += 32) {
                float hv = __ldcg(hrow + k);
                a0 += hv * w0[k];
                a1 += hv * w1[k];
            }
            #pragma unroll
            for (int s = 16; s; s >>= 1) {
                a0 += __shfl_xor_sync(0xffffffffu, a0, s);
                a1 += __shfl_xor_sync(0xffffffffu, a1, s);
            }
            if (lane == 0) { logits_s[bb * 4 + o0] = a0; logits_s[bb * 4 + o0 + 1] = a1; }
        }
        __syncthreads();
        if (tid < 2) {
            float l0 = logits_s[tid * 4 + 0], l1 = logits_s[tid * 4 + 1];
            float l2 = logits_s[tid * 4 + 2], l3 = logits_s[tid * 4 + 3];
            float mx = fmaxf(fmaxf(l0, l1), fmaxf(l2, l3));
            float e0 = expf(l0 - mx), e1 = expf(l1 - mx), e2 = expf(l2 - mx), e3 = expf(l3 - mx);
            float inv = 1.0f / (e0 + e1 + e2 + e3);
            size_t base = HID_ELEMS + ((size_t)(b0 + tid) * RNN_T + tp) * RNN_O;
            out[base + 0] = e0 * inv; out[base + 1] = e1 * inv;
            out[base + 2] = e2 * inv; out[base + 3] = e3 * inv;
        }
    }
}

// ---------------- launch ----------------
extern "C" void kernel_launch(void* const* d_in, const int* in_sizes, int n_in,
                              void* d_out, int out_size) {
    const float* x     = (const float*)d_in[0];
    const float* Win   = (const float*)d_in[1];
    const float* Wrec  = (const float*)d_in[2];
    const float* Wout  = (const float*)d_in[3];
    const float* noise = (const float*)d_in[4];
    float* out = (float*)d_out;

    cudaFuncSetAttribute(rnn_persistent_kernel,
                         cudaFuncAttributeMaxDynamicSharedMemorySize, SMEM_BYTES);
    rnn_persistent_kernel<<<GRID_CTAS, NTHREADS, SMEM_BYTES>>>(x, Win, Wrec, Wout, noise, out);
}

// round 9
// speedup vs baseline: 2.6116x; 1.2547x over previous
#include <cuda_runtime.h>
#include <cuda_bf16.h>
#include <cstdint>

// ---------------- problem constants ----------------
#define RNN_B 256
#define RNN_T 256
#define RNN_I 5
#define RNN_H 2048
#define RNN_O 4

#define GRID_CTAS 128
#define NTHREADS  512      // w0-7 GEMM, w8-11 producers, w12-15 softmax

// GEMM decomposition: 32 j-tiles (64 rows) x 4 k-slices (512 k)
#define JT_ROWS 64
#define KSLICE  512
#define NKSL    4
#define KC      32         // k per chunk (double buffered)
#define NCH     16         // KSLICE / KC
#define NJ      16         // epilogue rows per CTA

#define F_ALPHA 0.1f
#define F_BETA  0.9f

// SMEM row pads (bank-conflict-free fragment loads)
#define W_PITCH 520        // halfwords per Wrec row
#define H_PITCH 40         // halfwords per h row

// ---------------- shared memory layout (bytes) ----------------
#define WH_OFF   0                                   // 64*520*2 = 66560
#define WL_OFF   (WH_OFF + JT_ROWS * W_PITCH * 2)
#define HS_OFF   (WL_OFF + JT_ROWS * W_PITCH * 2)    // 133120
#define HS_BUF_STRIDE (2 * RNN_B * H_PITCH * 2)      // 40960 (hi+lo)
#define HS_ARR_STRIDE (RNN_B * H_PITCH * 2)          // 20480
#define XS_OFF   (HS_OFF + 2 * HS_BUF_STRIDE)        // 215040 (5120)
#define WIN_OFF  (XS_OFF + RNN_B * RNN_I * 4)        // 220160 (320)
#define LOG_OFF  (WIN_OFF + NJ * RNN_I * 4)          // 220480 (32)
#define SMEM_BYTES (LOG_OFF + 32)                    // 220512
// epilogue staging aliases the h ring (GEMM done by then)
#define NOISE_OFF (HS_OFF)
#define OUTS_OFF  (HS_OFF + RNN_B * 17 * 4)

#define HID_ELEMS ((size_t)RNN_B * RNN_T * RNN_H)

// ---------------- global scratch (static; no allocation) ----------------
static __device__ __nv_bfloat16 g_hhi[2 * RNN_B * RNN_H];   // [par][b][k]
static __device__ __nv_bfloat16 g_hlo[2 * RNN_B * RNN_H];
static __device__ float pre_part[NKSL * RNN_H * RNN_B];     // [ks][j][b]
static __device__ unsigned g_count;
static __device__ unsigned g_release;

// ---------------- helpers ----------------
__device__ __forceinline__ void cp_async16(void* dst, const void* src) {
    uint32_t sa = (uint32_t)__cvta_generic_to_shared(dst);
    asm volatile("cp.async.cg.shared.global [%0], [%1], 16;\n" :: "r"(sa), "l"(src) : "memory");
}
#define CP_COMMIT() asm volatile("cp.async.commit_group;\n" ::: "memory")
#define CP_WAIT0()  asm volatile("cp.async.wait_group 0;\n" ::: "memory")
#define BAR_GEMM()  asm volatile("bar.sync 2, 384;" ::: "memory")
#define BAR_SMAX()  asm volatile("bar.sync 1, 128;" ::: "memory")

__device__ __forceinline__ void grid_barrier() {
    __syncthreads();
    __threadfence();
    if (threadIdx.x == 0) {
        volatile unsigned* relp = (volatile unsigned*)&g_release;
        unsigned rel  = *relp;
        unsigned prev = atomicAdd(&g_count, 1u);
        if (prev == (unsigned)(GRID_CTAS - 1)) {
            atomicExch(&g_count, 0u);
            __threadfence();
            atomicAdd(&g_release, 1u);
        } else {
            while (*relp == rel) { }
        }
    }
    __syncthreads();
    __threadfence();
}

#define MMA_BF16(d, a0, a1, a2, a3, b0, b1)                                   \
    asm volatile("mma.sync.aligned.m16n8k16.row.col.f32.bf16.bf16.f32 "       \
                 "{%0,%1,%2,%3}, {%4,%5,%6,%7}, {%8,%9}, {%0,%1,%2,%3};"      \
                 : "+f"((d)[0]), "+f"((d)[1]), "+f"((d)[2]), "+f"((d)[3])     \
                 : "r"(a0), "r"(a1), "r"(a2), "r"(a3), "r"(b0), "r"(b1))

__device__ __forceinline__ uint32_t lds_u32(const __nv_bfloat16* base, int hw_idx) {
    return *(const uint32_t*)(base + hw_idx);
}

// producers (warps 8-11, ptid 0..127): load one 32-k chunk of h hi+lo
// FIX(R7): full chunk = 256 rows x 64 bytes = 1024 x 16B transfers per array
// (previous version loaded only 32 of 64 bytes per row -> garbage upper k-lanes).
__device__ __forceinline__ void load_chunk(char* smem, int slot,
                                           const __nv_bfloat16* ghi,
                                           const __nv_bfloat16* glo,
                                           int K0, int ch, int ptid) {
    char* dh = smem + HS_OFF + slot * HS_BUF_STRIDE;
    char* dl = dh + HS_ARR_STRIDE;
    const int kel = K0 + ch * KC;
    for (int i = ptid; i < 1024; i += 128) {    // 256 rows * 4 x 16B
        int b = i >> 2, q = i & 3;
        cp_async16(dh + b * (H_PITCH * 2) + q * 16, ghi + (size_t)b * RNN_H + kel + q * 8);
        cp_async16(dl + b * (H_PITCH * 2) + q * 16, glo + (size_t)b * RNN_H + kel + q * 8);
    }
    CP_COMMIT();
}

// ---------------- persistent kernel ----------------
__global__ void __launch_bounds__(NTHREADS, 1)
rnn_persistent_kernel(const float* __restrict__ x,     // [B,T,I]
                      const float* __restrict__ Win,   // [H,I]
                      const float* __restrict__ Wrec,  // [H,H]
                      const float* __restrict__ Wout,  // [O,H]
                      const float* __restrict__ noise, // [T,B,H]
                      float* __restrict__ out)         // hiddens [B,T,H] ++ outputs [B,T,O]
{
    extern __shared__ char smem[];
    __nv_bfloat16* Whi_s = (__nv_bfloat16*)(smem + WH_OFF);
    __nv_bfloat16* Wlo_s = (__nv_bfloat16*)(smem + WL_OFF);
    float* xs       = (float*)(smem + XS_OFF);
    float* Win_s    = (float*)(smem + WIN_OFF);
    float* logits_s = (float*)(smem + LOG_OFF);
    float* noise_s  = (float*)(smem + NOISE_OFF);
    float* out_s    = (float*)(smem + OUTS_OFF);

    const int tid  = threadIdx.x;
    const int lane = tid & 31;
    const int w    = tid >> 5;
    const int c    = blockIdx.x;

    const int jt = c >> 2;              // j-tile 0..31
    const int ks = c & 3;               // k-slice 0..3
    const int K0 = ks * KSLICE;
    const int jc = c * NJ;              // epilogue row base

    // GEMM warp tile: 32j x 64b  (2 m-tiles x 8 n-frags)
    const int jw = (w & 1) * 32;
    const int bw = (w >> 1) * 64;       // valid for w<8
    const int a_row = lane >> 2;
    const int a_col = (lane & 3) * 2;
    const int a_off0 = (jw + a_row) * W_PITCH + a_col;
    const int a_off1 = (jw + 16 + a_row) * W_PITCH + a_col;
    const int b_off  = (bw + a_row) * H_PITCH + a_col;

    // ---- one-time: split Wrec slice into SMEM bf16 hi/lo ----
    for (int i = tid; i < JT_ROWS * KSLICE; i += NTHREADS) {
        int jl = i >> 9, kk = i & (KSLICE - 1);
        float wv = Wrec[(size_t)(jt * JT_ROWS + jl) * RNN_H + K0 + kk];
        __nv_bfloat16 hi = __float2bfloat16_rn(wv);
        __nv_bfloat16 lo = __float2bfloat16_rn(wv - __bfloat162float(hi));
        Whi_s[jl * W_PITCH + kk] = hi;
        Wlo_s[jl * W_PITCH + kk] = lo;
    }
    for (int i = tid; i < NJ * RNN_I; i += NTHREADS) Win_s[i] = Win[jc * RNN_I + i];
    {   // zero h parity 0 (owned contiguous slice)
        uint32_t* ph = (uint32_t*)g_hhi;
        uint32_t* pl = (uint32_t*)g_hlo;
        for (int i = tid; i < 2048; i += NTHREADS) { ph[c * 2048 + i] = 0u; pl[c * 2048 + i] = 0u; }
    }
    float hprev[NJ];
    #pragma unroll
    for (int i = 0; i < NJ; ++i) hprev[i] = 0.0f;

    grid_barrier();   // h parity 0 + Wrec smem visible

    for (int t = 0; t < RNN_T; ++t) {
        const int rpar = t & 1;
        const __nv_bfloat16* ghi = g_hhi + (size_t)rpar * RNN_B * RNN_H;
        const __nv_bfloat16* glo = g_hlo + (size_t)rpar * RNN_B * RNN_H;

        if (w < 12) {
            // ================= GEMM + producer path =================
            float acc[2][8][4];
            if (w < 8) {
                #pragma unroll
                for (int mi = 0; mi < 2; ++mi)
                    #pragma unroll
                    for (int nf = 0; nf < 8; ++nf)
                        #pragma unroll
                        for (int q = 0; q < 4; ++q) acc[mi][nf][q] = 0.0f;
            } else {
                load_chunk(smem, 0, ghi, glo, K0, 0, tid - 256);
                CP_WAIT0();
            }
            BAR_GEMM();   // buf0 ready

            for (int ch = 0; ch < NCH; ++ch) {
                if (w < 8) {
                    const __nv_bfloat16* hhi =
                        (const __nv_bfloat16*)(smem + HS_OFF + (ch & 1) * HS_BUF_STRIDE);
                    const __nv_bfloat16* hlo =
                        (const __nv_bfloat16*)((const char*)hhi + HS_ARR_STRIDE);
                    #pragma unroll
                    for (int kk = 0; kk < KC; kk += 16) {
                        const int ka = ch * KC + kk;
                        uint32_t ah[2][4], al[2][4];
                        #pragma unroll
                        for (int mi = 0; mi < 2; ++mi) {
                            const int ao = (mi ? a_off1 : a_off0) + ka;
                            ah[mi][0] = lds_u32(Whi_s, ao);
                            ah[mi][1] = lds_u32(Whi_s, ao + 8 * W_PITCH);
                            ah[mi][2] = lds_u32(Whi_s, ao + 8);
                            ah[mi][3] = lds_u32(Whi_s, ao + 8 * W_PITCH + 8);
                            al[mi][0] = lds_u32(Wlo_s, ao);
                            al[mi][1] = lds_u32(Wlo_s, ao + 8 * W_PITCH);
                            al[mi][2] = lds_u32(Wlo_s, ao + 8);
                            al[mi][3] = lds_u32(Wlo_s, ao + 8 * W_PITCH + 8);
                        }
                        #pragma unroll
                        for (int nf = 0; nf < 8; ++nf) {
                            const int bb = b_off + nf * 8 * H_PITCH + kk;
                            uint32_t bh0 = lds_u32(hhi, bb);
                            uint32_t bh1 = lds_u32(hhi, bb + 8);
                            uint32_t bl0 = lds_u32(hlo, bb);
                            uint32_t bl1 = lds_u32(hlo, bb + 8);
                            #pragma unroll
                            for (int mi = 0; mi < 2; ++mi) {
                                MMA_BF16(acc[mi][nf], ah[mi][0], ah[mi][1], ah[mi][2], ah[mi][3], bh0, bh1);
                                MMA_BF16(acc[mi][nf], ah[mi][0], ah[mi][1], ah[mi][2], ah[mi][3], bl0, bl1);
                                MMA_BF16(acc[mi][nf], al[mi][0], al[mi][1], al[mi][2], al[mi][3], bh0, bh1);
                            }
                        }
                    }
                } else {
                    if (ch + 1 < NCH) {
                        load_chunk(smem, (ch + 1) & 1, ghi, glo, K0, ch + 1, tid - 256);
                        CP_WAIT0();
                    }
                }
                BAR_GEMM();   // buf[(ch+1)&1] ready; GEMM done with buf[ch&1]
            }

            // ---- partial store (GEMM warps) ----
            if (w < 8) {
                #pragma unroll
                for (int mi = 0; mi < 2; ++mi) {
                    const int j0 = jt * JT_ROWS + jw + mi * 16 + a_row;
                    #pragma unroll
                    for (int nf = 0; nf < 8; ++nf) {
                        const int bg = bw + nf * 8 + (lane & 3) * 2;
                        float2 v0 = make_float2(acc[mi][nf][0], acc[mi][nf][1]);
                        float2 v1 = make_float2(acc[mi][nf][2], acc[mi][nf][3]);
                        *(float2*)&pre_part[((size_t)ks * RNN_H + j0    ) * RNN_B + bg] = v0;
                        *(float2*)&pre_part[((size_t)ks * RNN_H + j0 + 8) * RNN_B + bg] = v1;
                    }
                }
            }
        } else if (t > 0) {
            // ================= softmax path (warps 12-15, fully concurrent) =================
            const int tp = t - 1;
            const int b0 = 2 * c;
            const int wq = w - 12;
            const int bb = wq >> 1;
            const int b  = b0 + bb;
            const int o0 = 2 * (wq & 1);
            const float* hrow = out + ((size_t)b * RNN_T + tp) * RNN_H;
            const float* w0 = Wout + (size_t)o0 * RNN_H;
            const float* w1 = Wout + (size_t)(o0 + 1) * RNN_H;
            float a0 = 0.f, a1 = 0.f;
            #pragma unroll 4
            for (int k = lane; k < RNN_H; k += 32) {
                float hv = __ldcg(hrow + k);
                a0 += hv * w0[k];
                a1 += hv * w1[k];
            }
            #pragma unroll
            for (int s = 16; s; s >>= 1) {
                a0 += __shfl_xor_sync(0xffffffffu, a0, s);
                a1 += __shfl_xor_sync(0xffffffffu, a1, s);
            }
            if (lane == 0) { logits_s[bb * 4 + o0] = a0; logits_s[bb * 4 + o0 + 1] = a1; }
            BAR_SMAX();
            if (tid - 384 < 2) {
                const int bt = tid - 384;
                float l0 = logits_s[bt * 4 + 0], l1 = logits_s[bt * 4 + 1];
                float l2 = logits_s[bt * 4 + 2], l3 = logits_s[bt * 4 + 3];
                float mx = fmaxf(fmaxf(l0, l1), fmaxf(l2, l3));
                float e0 = expf(l0 - mx), e1 = expf(l1 - mx), e2 = expf(l2 - mx), e3 = expf(l3 - mx);
                float inv = 1.0f / (e0 + e1 + e2 + e3);
                size_t base = HID_ELEMS + ((size_t)(b0 + bt) * RNN_T + tp) * RNN_O;
                out[base + 0] = e0 * inv; out[base + 1] = e1 * inv;
                out[base + 2] = e2 * inv; out[base + 3] = e3 * inv;
            }
        }

        grid_barrier();   // partials complete chip-wide

        // ---- epilogue: stage x and noise (coalesced, all threads) ----
        for (int i = tid; i < RNN_B * RNN_I; i += NTHREADS) {
            int b = i / RNN_I, ii = i % RNN_I;
            xs[i] = x[((size_t)b * RNN_T + t) * RNN_I + ii];
        }
        for (int i = tid; i < RNN_B * NJ; i += NTHREADS) {
            int b = i >> 4, jl = i & 15;
            noise_s[b * 17 + jl] = noise[((size_t)t * RNN_B + b) * RNN_H + jc + jl];
        }
        __syncthreads();

        // ---- leaky update: thread = batch b (first 256 threads) ----
        if (tid < RNN_B) {
            const int b = tid;
            #pragma unroll
            for (int jl = 0; jl < NJ; ++jl) {
                const size_t pbase = (size_t)(jc + jl) * RNN_B + b;
                float pre = __ldcg(&pre_part[0 * (size_t)RNN_H * RNN_B + pbase])
                          + __ldcg(&pre_part[1 * (size_t)RNN_H * RNN_B + pbase])
                          + __ldcg(&pre_part[2 * (size_t)RNN_H * RNN_B + pbase])
                          + __ldcg(&pre_part[3 * (size_t)RNN_H * RNN_B + pbase]);
                float itv = 0.0f;
                #pragma unroll
                for (int ii = 0; ii < RNN_I; ++ii)
                    itv += xs[b * RNN_I + ii] * Win_s[jl * RNN_I + ii];
                pre += itv + noise_s[b * 17 + jl];
                float hn = F_ALPHA * fmaxf(pre, 0.0f) + F_BETA * hprev[jl];
                hprev[jl] = hn;
                out_s[b * 17 + jl] = hn;
            }
        }
        __syncthreads();

        // ---- coalesced writeback: fp32 hidden + split-bf16 state ----
        {
            const int wpar = rpar ^ 1;
            __nv_bfloat16* dhi = g_hhi + (size_t)wpar * RNN_B * RNN_H;
            __nv_bfloat16* dlo = g_hlo + (size_t)wpar * RNN_B * RNN_H;
            for (int i = tid; i < RNN_B * NJ; i += NTHREADS) {
                int b = i >> 4, jl = i & 15;
                float hv = out_s[b * 17 + jl];
                out[((size_t)b * RNN_T + t) * RNN_H + jc + jl] = hv;
                __nv_bfloat16 hi = __float2bfloat16_rn(hv);
                __nv_bfloat16 lo = __float2bfloat16_rn(hv - __bfloat162float(hi));
                dhi[(size_t)b * RNN_H + jc + jl] = hi;
                dlo[(size_t)b * RNN_H + jc + jl] = lo;
            }
        }

        grid_barrier();   // h(t) complete chip-wide
    }

    // ---- final softmax for t = T-1 (warps 12-15) ----
    if (w >= 12) {
        const int tp = RNN_T - 1;
        const int b0 = 2 * c;
        const int wq = w - 12;
        const int bb = wq >> 1;
        const int b  = b0 + bb;
        const int o0 = 2 * (wq & 1);
        const float* hrow = out + ((size_t)b * RNN_T + tp) * RNN_H;
        const float* w0 = Wout + (size_t)o0 * RNN_H;
        const float* w1 = Wout + (size_t)(o0 + 1) * RNN_H;
        float a0 = 0.f, a1 = 0.f;
        #pragma unroll 4
        for (int k = lane; k < RNN_H; k += 32) {
            float hv = __ldcg(hrow + k);
            a0 += hv * w0[k];
            a1 += hv * w1[k];
        }
        #pragma unroll
        for (int s = 16; s; s >>= 1) {
            a0 += __shfl_xor_sync(0xffffffffu, a0, s);
            a1 += __shfl_xor_sync(0xffffffffu, a1, s);
        }
        if (lane == 0) { logits_s[bb * 4 + o0] = a0; logits_s[bb * 4 + o0 + 1] = a1; }
        BAR_SMAX();
        if (tid - 384 < 2) {
            const int bt = tid - 384;
            float l0 = logits_s[bt * 4 + 0], l1 = logits_s[bt * 4 + 1];
            float l2 = logits_s[bt * 4 + 2], l3 = logits_s[bt * 4 + 3];
            float mx = fmaxf(fmaxf(l0, l1), fmaxf(l2, l3));
            float e0 = expf(l0 - mx), e1 = expf(l1 - mx), e2 = expf(l2 - mx), e3 = expf(l3 - mx);
            float inv = 1.0f / (e0 + e1 + e2 + e3);
            size_t base = HID_ELEMS + ((size_t)(b0 + bt) * RNN_T + tp) * RNN_O;
            out[base + 0] = e0 * inv; out[base + 1] = e1 * inv;
            out[base + 2] = e2 * inv; out[base + 3] = e3 * inv;
        }
    }
}

// ---------------- launch ----------------
extern "C" void kernel_launch(void* const* d_in, const int* in_sizes, int n_in,
                              void* d_out, int out_size) {
    const float* x     = (const float*)d_in[0];
    const float* Win   = (const float*)d_in[1];
    const float* Wrec  = (const float*)d_in[2];
    const float* Wout  = (const float*)d_in[3];
    const float* noise = (const float*)d_in[4];
    float* out = (float*)d_out;

    cudaFuncSetAttribute(rnn_persistent_kernel,
                         cudaFuncAttributeMaxDynamicSharedMemorySize, SMEM_BYTES);
    rnn_persistent_kernel<<<GRID_CTAS, NTHREADS, SMEM_BYTES>>>(x, Win, Wrec, Wout, noise, out);
}

// round 10
// speedup vs baseline: 2.8317x; 1.0843x over previous
#include <cuda_runtime.h>
#include <cuda_bf16.h>
#include <cstdint>

// ---------------- problem constants ----------------
#define RNN_B 256
#define RNN_T 256
#define RNN_I 5
#define RNN_H 2048
#define RNN_O 4

#define GRID_CTAS 128
#define NTHREADS  512      // w0-7 GEMM, w8-11 producers, w12-15 softmax

// GEMM decomposition: 32 j-tiles (64 rows) x 4 k-slices (512 k)
#define JT_ROWS 64
#define KSLICE  512
#define NKSL    4
#define KC      32         // k per chunk (double buffered)
#define NCH     16         // KSLICE / KC
#define NJ      16         // epilogue rows per CTA

#define F_ALPHA 0.1f
#define F_BETA  0.9f

// SMEM row pads (bank-conflict-free LDSM)
#define W_PITCH 520        // halfwords per Wrec row (260 words: 4r mod 32 distinct)
#define H_PITCH 40         // halfwords per h row   (20 words: 20r mod 32 distinct)

// ---------------- shared memory layout (bytes) ----------------
#define WH_OFF   0                                   // 64*520*2 = 66560
#define WL_OFF   (WH_OFF + JT_ROWS * W_PITCH * 2)
#define HS_OFF   (WL_OFF + JT_ROWS * W_PITCH * 2)    // 133120
#define HS_BUF_STRIDE (2 * RNN_B * H_PITCH * 2)      // 40960 (hi+lo)
#define HS_ARR_STRIDE (RNN_B * H_PITCH * 2)          // 20480
#define WIN_OFF  (HS_OFF + 2 * HS_BUF_STRIDE)        // 215040 (320)
#define LOG_OFF  (WIN_OFF + NJ * RNN_I * 4)          // 215360 (32)
#define SMEM_BYTES (LOG_OFF + 32)

#define HID_ELEMS ((size_t)RNN_B * RNN_T * RNN_H)

// ---------------- global scratch (static; no allocation) ----------------
static __device__ __nv_bfloat16 g_hhi[2 * RNN_B * RNN_H];   // [par][b][k]
static __device__ __nv_bfloat16 g_hlo[2 * RNN_B * RNN_H];
static __device__ float pre_part[NKSL * RNN_H * RNN_B];     // [ks][j][b]
static __device__ unsigned g_count;
static __device__ unsigned g_release;
static __device__ unsigned g_grp[32];                       // per-jt-group arrive counters

// ---------------- helpers ----------------
__device__ __forceinline__ void cp_async16(void* dst, const void* src) {
    uint32_t sa = (uint32_t)__cvta_generic_to_shared(dst);
    asm volatile("cp.async.cg.shared.global [%0], [%1], 16;\n" :: "r"(sa), "l"(src) : "memory");
}
#define CP_COMMIT() asm volatile("cp.async.commit_group;\n" ::: "memory")
#define CP_WAIT0()  asm volatile("cp.async.wait_group 0;\n" ::: "memory")
#define BAR_GEMM()  asm volatile("bar.sync 2, 384;" ::: "memory")
#define BAR_SMAX()  asm volatile("bar.sync 1, 128;" ::: "memory")
#define BAR_REL()   asm volatile("bar.sync 3, 256;" ::: "memory")

__device__ __forceinline__ void grid_barrier() {
    __syncthreads();
    __threadfence();
    if (threadIdx.x == 0) {
        volatile unsigned* relp = (volatile unsigned*)&g_release;
        unsigned rel  = *relp;
        unsigned prev = atomicAdd(&g_count, 1u);
        if (prev == (unsigned)(GRID_CTAS - 1)) {
            atomicExch(&g_count, 0u);
            __threadfence();
            atomicAdd(&g_release, 1u);
        } else {
            while (*relp == rel) { }
        }
    }
    __syncthreads();
    __threadfence();
}

#define MMA_BF16(d, a0, a1, a2, a3, b0, b1)                                   \
    asm volatile("mma.sync.aligned.m16n8k16.row.col.f32.bf16.bf16.f32 "       \
                 "{%0,%1,%2,%3}, {%4,%5,%6,%7}, {%8,%9}, {%0,%1,%2,%3};"      \
                 : "+f"((d)[0]), "+f"((d)[1]), "+f"((d)[2]), "+f"((d)[3])     \
                 : "r"(a0), "r"(a1), "r"(a2), "r"(a3), "r"(b0), "r"(b1))

#define LDSM4(r, addr)                                                         \
    asm volatile("ldmatrix.sync.aligned.m8n8.x4.shared.b16 {%0,%1,%2,%3}, [%4];" \
                 : "=r"((r)[0]), "=r"((r)[1]), "=r"((r)[2]), "=r"((r)[3])      \
                 : "r"(addr))

// producers (warps 8-11, ptid 0..127): load one 32-k chunk of h hi+lo
__device__ __forceinline__ void load_chunk(char* smem, int slot,
                                           const __nv_bfloat16* ghi,
                                           const __nv_bfloat16* glo,
                                           int K0, int ch, int ptid) {
    char* dh = smem + HS_OFF + slot * HS_BUF_STRIDE;
    char* dl = dh + HS_ARR_STRIDE;
    const int kel = K0 + ch * KC;
    for (int i = ptid; i < 1024; i += 128) {    // 256 rows * 4 x 16B
        int b = i >> 2, q = i & 3;
        cp_async16(dh + b * (H_PITCH * 2) + q * 16, ghi + (size_t)b * RNN_H + kel + q * 8);
        cp_async16(dl + b * (H_PITCH * 2) + q * 16, glo + (size_t)b * RNN_H + kel + q * 8);
    }
    CP_COMMIT();
}

// ---------------- persistent kernel ----------------
__global__ void __launch_bounds__(NTHREADS, 1)
rnn_persistent_kernel(const float* __restrict__ x,     // [B,T,I]
                      const float* __restrict__ Win,   // [H,I]
                      const float* __restrict__ Wrec,  // [H,H]
                      const float* __restrict__ Wout,  // [O,H]
                      const float* __restrict__ noise, // [T,B,H]
                      float* __restrict__ out)         // hiddens [B,T,H] ++ outputs [B,T,O]
{
    extern __shared__ char smem[];
    __nv_bfloat16* Whi_s = (__nv_bfloat16*)(smem + WH_OFF);
    __nv_bfloat16* Wlo_s = (__nv_bfloat16*)(smem + WL_OFF);
    float* Win_s    = (float*)(smem + WIN_OFF);
    float* logits_s = (float*)(smem + LOG_OFF);

    const int tid  = threadIdx.x;
    const int lane = tid & 31;
    const int w    = tid >> 5;
    const int c    = blockIdx.x;

    const int jt = c >> 2;              // j-tile 0..31
    const int ks = c & 3;               // k-slice 0..3
    const int K0 = ks * KSLICE;
    const int jc = c * NJ;              // epilogue row base
    const int grp = c >> 2;             // jt group (4 CTAs: producers+consumers of its partials)

    // GEMM warp tile: 32j x 64b  (2 m-tiles x 8 n-frags), LDSM addressing
    const int jw = (w & 1) * 32;
    const int bw = (w >> 1) * 64;       // valid for w<8
    const int a_row = lane >> 2;

    const uint32_t smem_u32 = (uint32_t)__cvta_generic_to_shared(smem);
    // A LDSM per-lane offset (bytes): rows lane&15, k-col (lane>>4)*8
    const uint32_t a_lds_b = (uint32_t)((((lane & 15) * W_PITCH) + ((lane >> 4) << 3)) << 1);
    // B LDSM per-lane offset (bytes): n-row bw + (lane&7) + (lane>>4)*8, k-col ((lane>>3)&1)*8
    const uint32_t b_lds_b = (uint32_t)((((bw + (lane & 7) + ((lane >> 4) << 3)) * H_PITCH)
                                         + (((lane >> 3) & 1) << 3)) << 1);
    const uint32_t aw_hi0 = smem_u32 + WH_OFF + (uint32_t)(jw * W_PITCH * 2) + a_lds_b;
    const uint32_t aw_lo0 = smem_u32 + WL_OFF + (uint32_t)(jw * W_PITCH * 2) + a_lds_b;

    // ---- one-time: split Wrec slice into SMEM bf16 hi/lo ----
    for (int i = tid; i < JT_ROWS * KSLICE; i += NTHREADS) {
        int jl = i >> 9, kk = i & (KSLICE - 1);
        float wv = Wrec[(size_t)(jt * JT_ROWS + jl) * RNN_H + K0 + kk];
        __nv_bfloat16 hi = __float2bfloat16_rn(wv);
        __nv_bfloat16 lo = __float2bfloat16_rn(wv - __bfloat162float(hi));
        Whi_s[jl * W_PITCH + kk] = hi;
        Wlo_s[jl * W_PITCH + kk] = lo;
    }
    for (int i = tid; i < NJ * RNN_I; i += NTHREADS) Win_s[i] = Win[jc * RNN_I + i];
    {   // zero h parity 0 (owned contiguous slice)
        uint32_t* ph = (uint32_t*)g_hhi;
        uint32_t* pl = (uint32_t*)g_hlo;
        for (int i = tid; i < 2048; i += NTHREADS) { ph[c * 2048 + i] = 0u; pl[c * 2048 + i] = 0u; }
    }

    // epilogue role: thread owns (b = tid>>1, 8 rows starting at (tid&1)*8)
    const int eb   = tid >> 1;
    const int ejl0 = (tid & 1) * 8;
    float hprev[8];
    #pragma unroll
    for (int i = 0; i < 8; ++i) hprev[i] = 0.0f;

    // group-sync base (read BEFORE grid barrier: no one increments until after it)
    unsigned grp_base = 0;
    if (tid == 0) grp_base = *(volatile unsigned*)&g_grp[grp];

    grid_barrier();   // h parity 0 + Wrec smem visible

    for (int t = 0; t < RNN_T; ++t) {
        const int rpar = t & 1;
        const __nv_bfloat16* ghi = g_hhi + (size_t)rpar * RNN_B * RNN_H;
        const __nv_bfloat16* glo = g_hlo + (size_t)rpar * RNN_B * RNN_H;

        if (w < 12) {
            // ================= GEMM + producer path =================
            float acc[2][8][4];
            if (w < 8) {
                #pragma unroll
                for (int mi = 0; mi < 2; ++mi)
                    #pragma unroll
                    for (int nf = 0; nf < 8; ++nf)
                        #pragma unroll
                        for (int q = 0; q < 4; ++q) acc[mi][nf][q] = 0.0f;
            } else {
                load_chunk(smem, 0, ghi, glo, K0, 0, tid - 256);
                CP_WAIT0();
            }
            BAR_GEMM();   // buf0 ready

            for (int ch = 0; ch < NCH; ++ch) {
                if (w < 8) {
                    const uint32_t hhi_u = smem_u32 + HS_OFF + (uint32_t)((ch & 1) * HS_BUF_STRIDE) + b_lds_b;
                    const uint32_t hlo_u = hhi_u + HS_ARR_STRIDE;
                    #pragma unroll
                    for (int kk = 0; kk < KC; kk += 16) {
                        const uint32_t ka2 = (uint32_t)((ch * KC + kk) << 1);
                        uint32_t ah[2][4], al[2][4];
                        LDSM4(ah[0], aw_hi0 + ka2);
                        LDSM4(ah[1], aw_hi0 + (uint32_t)(16 * W_PITCH * 2) + ka2);
                        LDSM4(al[0], aw_lo0 + ka2);
                        LDSM4(al[1], aw_lo0 + (uint32_t)(16 * W_PITCH * 2) + ka2);
                        #pragma unroll
                        for (int p = 0; p < 4; ++p) {
                            const uint32_t bo = (uint32_t)(((p * 16 * H_PITCH) + kk) << 1);
                            uint32_t bh[4], bl[4];
                            LDSM4(bh, hhi_u + bo);
                            LDSM4(bl, hlo_u + bo);
                            #pragma unroll
                            for (int mi = 0; mi < 2; ++mi) {
                                MMA_BF16(acc[mi][2*p],   ah[mi][0], ah[mi][1], ah[mi][2], ah[mi][3], bh[0], bh[1]);
                                MMA_BF16(acc[mi][2*p],   ah[mi][0], ah[mi][1], ah[mi][2], ah[mi][3], bl[0], bl[1]);
                                MMA_BF16(acc[mi][2*p],   al[mi][0], al[mi][1], al[mi][2], al[mi][3], bh[0], bh[1]);
                                MMA_BF16(acc[mi][2*p+1], ah[mi][0], ah[mi][1], ah[mi][2], ah[mi][3], bh[2], bh[3]);
                                MMA_BF16(acc[mi][2*p+1], ah[mi][0], ah[mi][1], ah[mi][2], ah[mi][3], bl[2], bl[3]);
                                MMA_BF16(acc[mi][2*p+1], al[mi][0], al[mi][1], al[mi][2], al[mi][3], bh[2], bh[3]);
                            }
                        }
                    }
                } else {
                    if (ch + 1 < NCH) {
                        load_chunk(smem, (ch + 1) & 1, ghi, glo, K0, ch + 1, tid - 256);
                        CP_WAIT0();
                    }
                }
                BAR_GEMM();   // buf[(ch+1)&1] ready; GEMM done with buf[ch&1]
            }

            // ---- partial store (GEMM warps) + group release ----
            if (w < 8) {
                #pragma unroll
                for (int mi = 0; mi < 2; ++mi) {
                    const int j0 = jt * JT_ROWS + jw + mi * 16 + a_row;
                    #pragma unroll
                    for (int nf = 0; nf < 8; ++nf) {
                        const int bg = bw + nf * 8 + (lane & 3) * 2;
                        float2 v0 = make_float2(acc[mi][nf][0], acc[mi][nf][1]);
                        float2 v1 = make_float2(acc[mi][nf][2], acc[mi][nf][3]);
                        *(float2*)&pre_part[((size_t)ks * RNN_H + j0    ) * RNN_B + bg] = v0;
                        *(float2*)&pre_part[((size_t)ks * RNN_H + j0 + 8) * RNN_B + bg] = v1;
                    }
                }
                __threadfence();
                BAR_REL();
                if (tid == 0) atomicAdd(&g_grp[grp], 1u);   // release this CTA's partials
            }
        } else if (t > 0) {
            // ================= softmax path (warps 12-15, fully concurrent) =================
            const int tp = t - 1;
            const int b0 = 2 * c;
            const int wq = w - 12;
            const int bb = wq >> 1;
            const int b  = b0 + bb;
            const int o0 = 2 * (wq & 1);
            const float* hrow = out + ((size_t)b * RNN_T + tp) * RNN_H;
            const float* w0 = Wout + (size_t)o0 * RNN_H;
            const float* w1 = Wout + (size_t)(o0 + 1) * RNN_H;
            float a0 = 0.f, a1 = 0.f;
            #pragma unroll 4
            for (int k = lane; k < RNN_H; k += 32) {
                float hv = __ldcg(hrow + k);
                a0 += hv * w0[k];
                a1 += hv * w1[k];
            }
            #pragma unroll
            for (int s = 16; s; s >>= 1) {
                a0 += __shfl_xor_sync(0xffffffffu, a0, s);
                a1 += __shfl_xor_sync(0xffffffffu, a1, s);
            }
            if (lane == 0) { logits_s[bb * 4 + o0] = a0; logits_s[bb * 4 + o0 + 1] = a1; }
            BAR_SMAX();
            if (tid - 384 < 2) {
                const int bt = tid - 384;
                float l0 = logits_s[bt * 4 + 0], l1 = logits_s[bt * 4 + 1];
                float l2 = logits_s[bt * 4 + 2], l3 = logits_s[bt * 4 + 3];
                float mx = fmaxf(fmaxf(l0, l1), fmaxf(l2, l3));
                float e0 = expf(l0 - mx), e1 = expf(l1 - mx), e2 = expf(l2 - mx), e3 = expf(l3 - mx);
                float inv = 1.0f / (e0 + e1 + e2 + e3);
                size_t base = HID_ELEMS + ((size_t)(b0 + bt) * RNN_T + tp) * RNN_O;
                out[base + 0] = e0 * inv; out[base + 1] = e1 * inv;
                out[base + 2] = e2 * inv; out[base + 3] = e3 * inv;
            }
        }

        // ---- epilogue inputs: issue LDGs into regs BEFORE the group-sync spin ----
        float nz[8];
        *(float4*)&nz[0] = __ldcs((const float4*)(noise + ((size_t)t * RNN_B + eb) * RNN_H + jc + ejl0));
        *(float4*)&nz[4] = __ldcs((const float4*)(noise + ((size_t)t * RNN_B + eb) * RNN_H + jc + ejl0 + 4));
        float xv[RNN_I];
        #pragma unroll
        for (int ii = 0; ii < RNN_I; ++ii)
            xv[ii] = __ldg(&x[((size_t)eb * RNN_T + t) * RNN_I + ii]);

        // ---- group sync: wait for all 4 k-slice CTAs of this jt group ----
        if (tid == 0) {
            volatile unsigned* gp = (volatile unsigned*)&g_grp[grp];
            const unsigned target = 4u * (unsigned)(t + 1);
            while ((*gp - grp_base) < target) { }
        }
        __syncthreads();
        __threadfence();

        // ---- leaky update (all 512 threads, 8 rows each), direct stores ----
        {
            float hn8[8];
            #pragma unroll
            for (int jl = 0; jl < 8; ++jl) {
                const int j = ejl0 + jl;
                const size_t pbase = (size_t)(jc + j) * RNN_B + eb;
                float pre = __ldcg(&pre_part[0 * (size_t)RNN_H * RNN_B + pbase])
                          + __ldcg(&pre_part[1 * (size_t)RNN_H * RNN_B + pbase])
                          + __ldcg(&pre_part[2 * (size_t)RNN_H * RNN_B + pbase])
                          + __ldcg(&pre_part[3 * (size_t)RNN_H * RNN_B + pbase]);
                float itv = 0.0f;
                #pragma unroll
                for (int ii = 0; ii < RNN_I; ++ii)
                    itv += xv[ii] * Win_s[j * RNN_I + ii];
                pre += itv + nz[jl];
                float hn = F_ALPHA * fmaxf(pre, 0.0f) + F_BETA * hprev[jl];
                hprev[jl] = hn;
                hn8[jl] = hn;
            }
            // fp32 hidden (32B per thread, 64B per b with its pair)
            float* orow = out + ((size_t)eb * RNN_T + t) * RNN_H + jc + ejl0;
            *(float4*)(orow + 0) = make_float4(hn8[0], hn8[1], hn8[2], hn8[3]);
            *(float4*)(orow + 4) = make_float4(hn8[4], hn8[5], hn8[6], hn8[7]);
            // split-bf16 state (16B each)
            const int wpar = rpar ^ 1;
            __nv_bfloat16* dhi = g_hhi + (size_t)wpar * RNN_B * RNN_H + (size_t)eb * RNN_H + jc + ejl0;
            __nv_bfloat16* dlo = g_hlo + (size_t)wpar * RNN_B * RNN_H + (size_t)eb * RNN_H + jc + ejl0;
            uint32_t hp[4], lp[4];
            #pragma unroll
            for (int q = 0; q < 4; ++q) {
                __nv_bfloat162 h2 = __floats2bfloat162_rn(hn8[2*q], hn8[2*q+1]);
                float rx = hn8[2*q]   - __low2float(h2);
                float ry = hn8[2*q+1] - __high2float(h2);
                __nv_bfloat162 l2v = __floats2bfloat162_rn(rx, ry);
                hp[q] = *(uint32_t*)&h2;
                lp[q] = *(uint32_t*)&l2v;
            }
            *(uint4*)dhi = make_uint4(hp[0], hp[1], hp[2], hp[3]);
            *(uint4*)dlo = make_uint4(lp[0], lp[1], lp[2], lp[3]);
        }

        grid_barrier();   // h(t) + hiddens complete chip-wide
    }

    // ---- final softmax for t = T-1 (warps 12-15) ----
    if (w >= 12) {
        const int tp = RNN_T - 1;
        const int b0 = 2 * c;
        const int wq = w - 12;
        const int bb = wq >> 1;
        const int b  = b0 + bb;
        const int o0 = 2 * (wq & 1);
        const float* hrow = out + ((size_t)b * RNN_T + tp) * RNN_H;
        const float* w0 = Wout + (size_t)o0 * RNN_H;
        const float* w1 = Wout + (size_t)(o0 + 1) * RNN_H;
        float a0 = 0.f, a1 = 0.f;
        #pragma unroll 4
        for (int k = lane; k < RNN_H; k += 32) {
            float hv = __ldcg(hrow + k);
            a0 += hv * w0[k];
            a1 += hv * w1[k];
        }
        #pragma unroll
        for (int s = 16; s; s >>= 1) {
            a0 += __shfl_xor_sync(0xffffffffu, a0, s);
            a1 += __shfl_xor_sync(0xffffffffu, a1, s);
        }
        if (lane == 0) { logits_s[bb * 4 + o0] = a0; logits_s[bb * 4 + o0 + 1] = a1; }
        BAR_SMAX();
        if (tid - 384 < 2) {
            const int bt = tid - 384;
            float l0 = logits_s[bt * 4 + 0], l1 = logits_s[bt * 4 + 1];
            float l2 = logits_s[bt * 4 + 2], l3 = logits_s[bt * 4 + 3];
            float mx = fmaxf(fmaxf(l0, l1), fmaxf(l2, l3));
            float e0 = expf(l0 - mx), e1 = expf(l1 - mx), e2 = expf(l2 - mx), e3 = expf(l3 - mx);
            float inv = 1.0f / (e0 + e1 + e2 + e3);
            size_t base = HID_ELEMS + ((size_t)(b0 + bt) * RNN_T + tp) * RNN_O;
            out[base + 0] = e0 * inv; out[base + 1] = e1 * inv;
            out[base + 2] = e2 * inv; out[base + 3] = e3 * inv;
        }
    }
}

// ---------------- launch ----------------
extern "C" void kernel_launch(void* const* d_in, const int* in_sizes, int n_in,
                              void* d_out, int out_size) {
    const float* x     = (const float*)d_in[0];
    const float* Win   = (const float*)d_in[1];
    const float* Wrec  = (const float*)d_in[2];
    const float* Wout  = (const float*)d_in[3];
    const float* noise = (const float*)d_in[4];
    float* out = (float*)d_out;

    cudaFuncSetAttribute(rnn_persistent_kernel,
                         cudaFuncAttributeMaxDynamicSharedMemorySize, SMEM_BYTES);
    rnn_persistent_kernel<<<GRID_CTAS, NTHREADS, SMEM_BYTES>>>(x, Win, Wrec, Wout, noise, out);
}